// round 1
// baseline (speedup 1.0000x reference)
#include <cuda_runtime.h>
#include <cstdint>
#include <cstddef>

#define SEQ     4096
#define DMODEL  2048
#define DH      128

// Scratch (allocation-free rule: __device__ globals)
__device__ float g_Q[SEQ * DH];
__device__ float g_K[SEQ * DH];
__device__ float g_V[SEQ * DH];

__device__ __forceinline__ uint32_t f2tf(float x) {
    uint32_t r;
    asm("cvt.rna.tf32.f32 %0, %1;" : "=r"(r) : "f"(x));
    return r;
}

__device__ __forceinline__ void mma_tf32(float d[4], const uint32_t a[4],
                                         uint32_t b0, uint32_t b1) {
    asm volatile(
        "mma.sync.aligned.m16n8k8.row.col.f32.tf32.tf32.f32 "
        "{%0,%1,%2,%3},{%4,%5,%6,%7},{%8,%9},{%0,%1,%2,%3};\n"
        : "+f"(d[0]), "+f"(d[1]), "+f"(d[2]), "+f"(d[3])
        : "r"(a[0]), "r"(a[1]), "r"(a[2]), "r"(a[3]), "r"(b0), "r"(b1));
}

// ---------------------------------------------------------------------------
// Projection: out[m, n] = X[m, :] . W[n, :] + b[n]
// X: [4096, 2048], W: [128, 2048], out: [4096, 128]
// Block = 256 thr (8 warps), tile 128(M) x 128(N), K-loop step 32.
// Warp tile: 32(M) x 64(N). grid = (32, 3) -> Q/K/V.
// ---------------------------------------------------------------------------
#define PSTR 36   // smem row stride (floats): bank = (4*row + k) % 32, conflict-free

__global__ __launch_bounds__(256, 1)
void proj_kernel(const float* __restrict__ xq, const float* __restrict__ xk,
                 const float* __restrict__ xv,
                 const float* __restrict__ wq, const float* __restrict__ bq,
                 const float* __restrict__ wk, const float* __restrict__ bk,
                 const float* __restrict__ wv, const float* __restrict__ bv) {
    __shared__ float Xs[128][PSTR];
    __shared__ float Ws[128][PSTR];

    const float* X; const float* W; const float* bias; float* out;
    if (blockIdx.y == 0)      { X = xq; W = wq; bias = bq; out = g_Q; }
    else if (blockIdx.y == 1) { X = xk; W = wk; bias = bk; out = g_K; }
    else                      { X = xv; W = wv; bias = bv; out = g_V; }

    const int tid  = threadIdx.x;
    const int warp = tid >> 5, lane = tid & 31;
    const int g    = lane >> 2, t4 = lane & 3;
    const int wm   = warp >> 1;   // 0..3 : 32 M-rows each
    const int wn   = warp & 1;    // 0..1 : 64 N-cols each
    const int m0   = blockIdx.x * 128;

    float acc[2][8][4] = {};

    float4 xr[4], wr[4];
    auto ld = [&](int k0) {
#pragma unroll
        for (int t = 0; t < 4; ++t) {
            int i = tid + t * 256;
            int r = i >> 3, c4 = (i & 7) * 4;
            xr[t] = *(const float4*)(X + (size_t)(m0 + r) * DMODEL + k0 + c4);
            wr[t] = *(const float4*)(W + (size_t)r * DMODEL + k0 + c4);
        }
    };
    auto st = [&]() {
#pragma unroll
        for (int t = 0; t < 4; ++t) {
            int i = tid + t * 256;
            int r = i >> 3, c4 = (i & 7) * 4;
            *(float4*)&Xs[r][c4] = xr[t];
            *(float4*)&Ws[r][c4] = wr[t];
        }
    };

    ld(0); st();
    __syncthreads();

    for (int k0 = 0; k0 < DMODEL; k0 += 32) {
        bool more = (k0 + 32 < DMODEL);
        if (more) ld(k0 + 32);   // overlap global fetch with MMA

#pragma unroll
        for (int kk = 0; kk < 32; kk += 8) {
            uint32_t a[2][4];
            uint32_t b[8][2];
#pragma unroll
            for (int mt = 0; mt < 2; ++mt) {
                int r = wm * 32 + mt * 16 + g;
                int c = kk + t4;
                a[mt][0] = f2tf(Xs[r][c]);
                a[mt][1] = f2tf(Xs[r + 8][c]);
                a[mt][2] = f2tf(Xs[r][c + 4]);
                a[mt][3] = f2tf(Xs[r + 8][c + 4]);
            }
#pragma unroll
            for (int nt = 0; nt < 8; ++nt) {
                int n = wn * 64 + nt * 8 + g;
                int c = kk + t4;
                b[nt][0] = f2tf(Ws[n][c]);
                b[nt][1] = f2tf(Ws[n][c + 4]);
            }
#pragma unroll
            for (int mt = 0; mt < 2; ++mt)
#pragma unroll
                for (int nt = 0; nt < 8; ++nt)
                    mma_tf32(acc[mt][nt], a[mt], b[nt][0], b[nt][1]);
        }
        __syncthreads();
        if (more) { st(); __syncthreads(); }
    }

#pragma unroll
    for (int mt = 0; mt < 2; ++mt) {
#pragma unroll
        for (int nt = 0; nt < 8; ++nt) {
            int r = m0 + wm * 32 + mt * 16 + g;
            int c = wn * 64 + nt * 8 + t4 * 2;
            float b0 = bias[c], b1 = bias[c + 1];
            out[(size_t)r * DH + c]           = acc[mt][nt][0] + b0;
            out[(size_t)r * DH + c + 1]       = acc[mt][nt][1] + b1;
            out[(size_t)(r + 8) * DH + c]     = acc[mt][nt][2] + b0;
            out[(size_t)(r + 8) * DH + c + 1] = acc[mt][nt][3] + b1;
        }
    }
}

// ---------------------------------------------------------------------------
// Causal flash attention, fp32 softmax, tf32 MMAs.
// Block = 128 thr (4 warps), BM=64 query rows/block, BN=32 keys/tile.
// Warp owns 16 query rows; Q kept in registers as tf32 fragments.
// scores = (Q K^T + mask) / sqrt(2048)  ==  scale-then-(-inf)-mask.
// ---------------------------------------------------------------------------
#define BM 64
#define BN 32
#define KSTR 132   // Ks accessed [n][k]: bank = (4n + k) % 32, conflict-free
#define VSTR 136   // Vs accessed [k][n]: bank = (8k + n) % 32, conflict-free

__global__ __launch_bounds__(128, 1)
void attn_kernel(float* __restrict__ out) {
    __shared__ float Ks[BN][KSTR];
    __shared__ float Vs[BN][VSTR];
    __shared__ float Ps[4][16][36];

    const int tid  = threadIdx.x;
    const int warp = tid >> 5, lane = tid & 31;
    const int g    = lane >> 2, t4 = lane & 3;
    const int qm0  = blockIdx.x * BM;
    const int row_base = qm0 + warp * 16;
    const float NEG_INF = __int_as_float(0xff800000u);
    const float scale = 0.02209708691207961f;  // 1/sqrt(2048)

    // Q fragments (16 rows x 128 cols per warp), resident all kernel
    uint32_t qf[16][4];
#pragma unroll
    for (int kt = 0; kt < 16; ++kt) {
        const float* qp = g_Q + (size_t)(row_base + g) * DH + kt * 8 + t4;
        qf[kt][0] = f2tf(qp[0]);
        qf[kt][1] = f2tf(qp[8 * DH]);
        qf[kt][2] = f2tf(qp[4]);
        qf[kt][3] = f2tf(qp[8 * DH + 4]);
    }

    float acc[16][4] = {};
    float m0r = NEG_INF, m1r = NEG_INF;
    float l0 = 0.f, l1 = 0.f;

    const int ntiles = (qm0 + BM) / BN;   // causal: 2*blockIdx.x + 2
    for (int j = 0; j < ntiles; ++j) {
        const int n0 = j * BN;

        // stage K/V tile (32 x 128) into smem
#pragma unroll
        for (int t = 0; t < 8; ++t) {
            int i = tid + t * 128;
            int r = i >> 5, c4 = (i & 31) * 4;
            *(float4*)&Ks[r][c4] = *(const float4*)(g_K + (size_t)(n0 + r) * DH + c4);
            *(float4*)&Vs[r][c4] = *(const float4*)(g_V + (size_t)(n0 + r) * DH + c4);
        }
        __syncthreads();

        // S = Q . K^T  (16 x 32 per warp)
        float s[4][4] = {};
#pragma unroll
        for (int kt = 0; kt < 16; ++kt) {
#pragma unroll
            for (int nt = 0; nt < 4; ++nt) {
                int n = nt * 8 + g;
                int c = kt * 8 + t4;
                uint32_t b0 = f2tf(Ks[n][c]);
                uint32_t b1 = f2tf(Ks[n][c + 4]);
                mma_tf32(s[nt], qf[kt], b0, b1);
            }
        }

        // scale + causal mask
        const int r0g = row_base + g, r1g = r0g + 8;
        const bool domask = (n0 + BN - 1 > row_base);
#pragma unroll
        for (int nt = 0; nt < 4; ++nt) {
            int c0 = n0 + nt * 8 + t4 * 2;
#pragma unroll
            for (int e = 0; e < 4; ++e) s[nt][e] *= scale;
            if (domask) {
                if (c0 > r0g)     s[nt][0] = NEG_INF;
                if (c0 + 1 > r0g) s[nt][1] = NEG_INF;
                if (c0 > r1g)     s[nt][2] = NEG_INF;
                if (c0 + 1 > r1g) s[nt][3] = NEG_INF;
            }
        }

        // online softmax: row max (quad = 4 threads per row)
        float mx0 = fmaxf(fmaxf(s[0][0], s[0][1]), fmaxf(s[1][0], s[1][1]));
        mx0 = fmaxf(mx0, fmaxf(fmaxf(s[2][0], s[2][1]), fmaxf(s[3][0], s[3][1])));
        float mx1 = fmaxf(fmaxf(s[0][2], s[0][3]), fmaxf(s[1][2], s[1][3]));
        mx1 = fmaxf(mx1, fmaxf(fmaxf(s[2][2], s[2][3]), fmaxf(s[3][2], s[3][3])));
        mx0 = fmaxf(mx0, __shfl_xor_sync(0xffffffffu, mx0, 1));
        mx0 = fmaxf(mx0, __shfl_xor_sync(0xffffffffu, mx0, 2));
        mx1 = fmaxf(mx1, __shfl_xor_sync(0xffffffffu, mx1, 1));
        mx1 = fmaxf(mx1, __shfl_xor_sync(0xffffffffu, mx1, 2));

        float mn0 = fmaxf(m0r, mx0), mn1 = fmaxf(m1r, mx1);
        float mu0 = fmaxf(mn0, -1e30f), mu1 = fmaxf(mn1, -1e30f);  // -inf-safe
        float al0 = __expf(m0r - mu0), al1 = __expf(m1r - mu1);
        m0r = mn0; m1r = mn1;

        float rs0 = 0.f, rs1 = 0.f;
#pragma unroll
        for (int nt = 0; nt < 4; ++nt) {
            float p00 = __expf(s[nt][0] - mu0), p01 = __expf(s[nt][1] - mu0);
            float p10 = __expf(s[nt][2] - mu1), p11 = __expf(s[nt][3] - mu1);
            rs0 += p00 + p01; rs1 += p10 + p11;
            Ps[warp][g][nt * 8 + t4 * 2]         = p00;
            Ps[warp][g][nt * 8 + t4 * 2 + 1]     = p01;
            Ps[warp][g + 8][nt * 8 + t4 * 2]     = p10;
            Ps[warp][g + 8][nt * 8 + t4 * 2 + 1] = p11;
        }
        rs0 += __shfl_xor_sync(0xffffffffu, rs0, 1);
        rs0 += __shfl_xor_sync(0xffffffffu, rs0, 2);
        rs1 += __shfl_xor_sync(0xffffffffu, rs1, 1);
        rs1 += __shfl_xor_sync(0xffffffffu, rs1, 2);
        l0 = l0 * al0 + rs0;
        l1 = l1 * al1 + rs1;

#pragma unroll
        for (int nt = 0; nt < 16; ++nt) {
            acc[nt][0] *= al0; acc[nt][1] *= al0;
            acc[nt][2] *= al1; acc[nt][3] *= al1;
        }
        __syncwarp();

        // O += P . V   (P: 16 x 32 from per-warp smem, V: 32 x 128)
#pragma unroll
        for (int ks = 0; ks < 4; ++ks) {
            uint32_t a[4];
            a[0] = f2tf(Ps[warp][g][ks * 8 + t4]);
            a[1] = f2tf(Ps[warp][g + 8][ks * 8 + t4]);
            a[2] = f2tf(Ps[warp][g][ks * 8 + t4 + 4]);
            a[3] = f2tf(Ps[warp][g + 8][ks * 8 + t4 + 4]);
#pragma unroll
            for (int nt = 0; nt < 16; ++nt) {
                int vn = nt * 8 + g;
                int vk = ks * 8 + t4;
                uint32_t b0 = f2tf(Vs[vk][vn]);
                uint32_t b1 = f2tf(Vs[vk + 4][vn]);
                mma_tf32(acc[nt], a, b0, b1);
            }
        }
        __syncthreads();   // protect Ks/Vs before next tile load
    }

    // epilogue: normalize and store
    const float inv0 = 1.0f / l0, inv1 = 1.0f / l1;
#pragma unroll
    for (int nt = 0; nt < 16; ++nt) {
        int r = row_base + g;
        int c = nt * 8 + t4 * 2;
        out[(size_t)r * DH + c]           = acc[nt][0] * inv0;
        out[(size_t)r * DH + c + 1]       = acc[nt][1] * inv0;
        out[(size_t)(r + 8) * DH + c]     = acc[nt][2] * inv1;
        out[(size_t)(r + 8) * DH + c + 1] = acc[nt][3] * inv1;
    }
}

// ---------------------------------------------------------------------------

extern "C" void kernel_launch(void* const* d_in, const int* in_sizes, int n_in,
                              void* d_out, int out_size) {
    (void)in_sizes; (void)n_in; (void)out_size;
    const float* xq = (const float*)d_in[0];
    const float* xk = (const float*)d_in[1];
    const float* xv = (const float*)d_in[2];
    const float* wq = (const float*)d_in[3];
    const float* bq = (const float*)d_in[4];
    const float* wk = (const float*)d_in[5];
    const float* bk = (const float*)d_in[6];
    const float* wv = (const float*)d_in[7];
    const float* bv = (const float*)d_in[8];
    float* out = (float*)d_out;

    dim3 gp(SEQ / 128, 3);
    proj_kernel<<<gp, 256>>>(xq, xk, xv, wq, bq, wk, bk, wv, bv);
    attn_kernel<<<SEQ / BM, 128>>>(out);
}

// round 3
// speedup vs baseline: 2.1428x; 2.1428x over previous
#include <cuda_runtime.h>
#include <cstdint>
#include <cstddef>

#define SEQ     4096
#define DMODEL  2048
#define DH      128
#define CHUNK   512          // keys per split-KV work unit
#define MAXC    8            // max chunks per q-tile (4096/512)

// Scratch (allocation-free rule: __device__ globals)
__device__ float g_Q[SEQ * DH];
__device__ float g_K[SEQ * DH];
__device__ float g_V[SEQ * DH];
// split-KV partials: [64 q-tiles][8 chunks][64 rows][128 cols]
__device__ float g_Opart[64 * MAXC * 64 * DH];
__device__ float g_mpart[64 * MAXC * 64];
__device__ float g_lpart[64 * MAXC * 64];

__device__ __forceinline__ uint32_t f2tf(float x) {
    uint32_t r;
    asm("cvt.rna.tf32.f32 %0, %1;" : "=r"(r) : "f"(x));
    return r;
}
__device__ __forceinline__ float ex2(float x) {
    float y;
    asm("ex2.approx.ftz.f32 %0, %1;" : "=f"(y) : "f"(x));
    return y;
}

__device__ __forceinline__ void mma_tf32(float d[4], const uint32_t a[4],
                                         uint32_t b0, uint32_t b1) {
    asm volatile(
        "mma.sync.aligned.m16n8k8.row.col.f32.tf32.tf32.f32 "
        "{%0,%1,%2,%3},{%4,%5,%6,%7},{%8,%9},{%0,%1,%2,%3};\n"
        : "+f"(d[0]), "+f"(d[1]), "+f"(d[2]), "+f"(d[3])
        : "r"(a[0]), "r"(a[1]), "r"(a[2]), "r"(a[3]), "r"(b0), "r"(b1));
}

// ---------------------------------------------------------------------------
// Projection: out[m, n] = tf32_round(X[m,:] . W[n,:] + b[n])
// Tile 64(M) x 128(N) per block of 256 thr; grid (64, 3).
// Output pre-rounded to tf32 so attention needs NO cvt in its hot loop.
// ---------------------------------------------------------------------------
#define PSTR 36   // bank = (4*row + k) % 32, conflict-free

__global__ __launch_bounds__(256, 2)
void proj_kernel(const float* __restrict__ xq, const float* __restrict__ xk,
                 const float* __restrict__ xv,
                 const float* __restrict__ wq, const float* __restrict__ bq,
                 const float* __restrict__ wk, const float* __restrict__ bk,
                 const float* __restrict__ wv, const float* __restrict__ bv) {
    __shared__ float Xs[64][PSTR];
    __shared__ float Ws[128][PSTR];

    const float* X; const float* W; const float* bias; float* out;
    if (blockIdx.y == 0)      { X = xq; W = wq; bias = bq; out = g_Q; }
    else if (blockIdx.y == 1) { X = xk; W = wk; bias = bk; out = g_K; }
    else                      { X = xv; W = wv; bias = bv; out = g_V; }

    const int tid  = threadIdx.x;
    const int warp = tid >> 5, lane = tid & 31;
    const int g    = lane >> 2, t4 = lane & 3;
    const int wm   = warp >> 1;   // 0..3 : 16 M-rows each
    const int wn   = warp & 1;    // 0..1 : 64 N-cols each
    const int m0   = blockIdx.x * 64;

    float acc[8][4] = {};

    float4 xr[2], wr[4];
    auto ld = [&](int k0) {
#pragma unroll
        for (int t = 0; t < 2; ++t) {
            int i = tid + t * 256;
            int r = i >> 3, c4 = (i & 7) * 4;
            xr[t] = *(const float4*)(X + (size_t)(m0 + r) * DMODEL + k0 + c4);
        }
#pragma unroll
        for (int t = 0; t < 4; ++t) {
            int i = tid + t * 256;
            int r = i >> 3, c4 = (i & 7) * 4;
            wr[t] = *(const float4*)(W + (size_t)r * DMODEL + k0 + c4);
        }
    };
    auto st = [&]() {
#pragma unroll
        for (int t = 0; t < 2; ++t) {
            int i = tid + t * 256;
            int r = i >> 3, c4 = (i & 7) * 4;
            *(float4*)&Xs[r][c4] = xr[t];
        }
#pragma unroll
        for (int t = 0; t < 4; ++t) {
            int i = tid + t * 256;
            int r = i >> 3, c4 = (i & 7) * 4;
            *(float4*)&Ws[r][c4] = wr[t];
        }
    };

    ld(0); st();
    __syncthreads();

    for (int k0 = 0; k0 < DMODEL; k0 += 32) {
        bool more = (k0 + 32 < DMODEL);
        if (more) ld(k0 + 32);

#pragma unroll
        for (int kk = 0; kk < 32; kk += 8) {
            uint32_t a[4];
            {
                int r = wm * 16 + g;
                int c = kk + t4;
                a[0] = f2tf(Xs[r][c]);
                a[1] = f2tf(Xs[r + 8][c]);
                a[2] = f2tf(Xs[r][c + 4]);
                a[3] = f2tf(Xs[r + 8][c + 4]);
            }
#pragma unroll
            for (int nt = 0; nt < 8; ++nt) {
                int n = wn * 64 + nt * 8 + g;
                int c = kk + t4;
                uint32_t b0 = f2tf(Ws[n][c]);
                uint32_t b1 = f2tf(Ws[n][c + 4]);
                mma_tf32(acc[nt], a, b0, b1);
            }
        }
        __syncthreads();
        if (more) { st(); __syncthreads(); }
    }

#pragma unroll
    for (int nt = 0; nt < 8; ++nt) {
        int r = m0 + wm * 16 + g;
        int c = wn * 64 + nt * 8 + t4 * 2;
        float b0 = bias[c], b1 = bias[c + 1];
        out[(size_t)r * DH + c]           = __uint_as_float(f2tf(acc[nt][0] + b0));
        out[(size_t)r * DH + c + 1]       = __uint_as_float(f2tf(acc[nt][1] + b1));
        out[(size_t)(r + 8) * DH + c]     = __uint_as_float(f2tf(acc[nt][2] + b0));
        out[(size_t)(r + 8) * DH + c + 1] = __uint_as_float(f2tf(acc[nt][3] + b1));
    }
}

// ---------------------------------------------------------------------------
// Split-KV causal flash attention. grid = (64 q-tiles, 8 chunks), 128 thr.
// Block (qt, c) processes queries [64*qt, 64*qt+64) x keys [512c, min(512c+512, 64(qt+1))).
// Softmax runs in exp2 domain; partials (unnormalized O, m, l) go to scratch,
// except single-chunk q-tiles which write the final output directly.
// ---------------------------------------------------------------------------
#define BM 64
#define BN 32
#define KSTR 132   // bank = (4n + k) % 32, conflict-free
#define VSTR 136   // bank = (8k + n) % 32, conflict-free

__global__ __launch_bounds__(128, 2)
void attn_kernel(float* __restrict__ out) {
    const int qt = blockIdx.x;
    const int ch = blockIdx.y;
    const int nc = (qt >> 3) + 1;          // ceil(64(qt+1)/512)
    if (ch >= nc) return;

    __shared__ float Ks[BN][KSTR];
    __shared__ float Vs[BN][VSTR];
    __shared__ float Ps[4][16][36];

    const int tid  = threadIdx.x;
    const int warp = tid >> 5, lane = tid & 31;
    const int g    = lane >> 2, t4 = lane & 3;
    const int qm0  = qt * BM;
    const int row_base = qm0 + warp * 16;
    const float NEG_INF = __int_as_float(0xff800000u);
    // (1/sqrt(2048)) * log2(e): fold scale into exp2 domain
    const float SC = 0.02209708691207961f * 1.4426950408889634f;

    const int kstart = ch * CHUNK;
    const int kend   = min(kstart + CHUNK, qm0 + BM);
    const int ntiles = (kend - kstart) / BN;

    // Q fragments: already tf32-rounded by proj -> raw bits
    uint32_t qf[16][4];
#pragma unroll
    for (int kt = 0; kt < 16; ++kt) {
        const float* qp = g_Q + (size_t)(row_base + g) * DH + kt * 8 + t4;
        qf[kt][0] = __float_as_uint(qp[0]);
        qf[kt][1] = __float_as_uint(qp[8 * DH]);
        qf[kt][2] = __float_as_uint(qp[4]);
        qf[kt][3] = __float_as_uint(qp[8 * DH + 4]);
    }

    float acc[16][4] = {};
    float m0r = NEG_INF, m1r = NEG_INF;
    float l0 = 0.f, l1 = 0.f;

    for (int j = 0; j < ntiles; ++j) {
        const int n0 = kstart + j * BN;

        // stage K/V tile (32 x 128)
#pragma unroll
        for (int t = 0; t < 8; ++t) {
            int i = tid + t * 128;
            int r = i >> 5, c4 = (i & 31) * 4;
            *(float4*)&Ks[r][c4] = *(const float4*)(g_K + (size_t)(n0 + r) * DH + c4);
            *(float4*)&Vs[r][c4] = *(const float4*)(g_V + (size_t)(n0 + r) * DH + c4);
        }
        __syncthreads();

        // S = Q . K^T  (16 x 32 per warp); K bits already tf32
        float s[4][4] = {};
#pragma unroll
        for (int kt = 0; kt < 16; ++kt) {
#pragma unroll
            for (int nt = 0; nt < 4; ++nt) {
                int n = nt * 8 + g;
                int c = kt * 8 + t4;
                uint32_t b0 = __float_as_uint(Ks[n][c]);
                uint32_t b1 = __float_as_uint(Ks[n][c + 4]);
                mma_tf32(s[nt], qf[kt], b0, b1);
            }
        }

        // exp2-domain scale + causal mask
        const int r0g = row_base + g, r1g = r0g + 8;
        const bool domask = (n0 + BN - 1 > row_base);
#pragma unroll
        for (int nt = 0; nt < 4; ++nt) {
            int c0 = n0 + nt * 8 + t4 * 2;
#pragma unroll
            for (int e = 0; e < 4; ++e) s[nt][e] *= SC;
            if (domask) {
                if (c0 > r0g)     s[nt][0] = NEG_INF;
                if (c0 + 1 > r0g) s[nt][1] = NEG_INF;
                if (c0 > r1g)     s[nt][2] = NEG_INF;
                if (c0 + 1 > r1g) s[nt][3] = NEG_INF;
            }
        }

        // online softmax (quad = 4 threads per row)
        float mx0 = fmaxf(fmaxf(s[0][0], s[0][1]), fmaxf(s[1][0], s[1][1]));
        mx0 = fmaxf(mx0, fmaxf(fmaxf(s[2][0], s[2][1]), fmaxf(s[3][0], s[3][1])));
        float mx1 = fmaxf(fmaxf(s[0][2], s[0][3]), fmaxf(s[1][2], s[1][3]));
        mx1 = fmaxf(mx1, fmaxf(fmaxf(s[2][2], s[2][3]), fmaxf(s[3][2], s[3][3])));
        mx0 = fmaxf(mx0, __shfl_xor_sync(0xffffffffu, mx0, 1));
        mx0 = fmaxf(mx0, __shfl_xor_sync(0xffffffffu, mx0, 2));
        mx1 = fmaxf(mx1, __shfl_xor_sync(0xffffffffu, mx1, 1));
        mx1 = fmaxf(mx1, __shfl_xor_sync(0xffffffffu, mx1, 2));

        float mn0 = fmaxf(m0r, mx0), mn1 = fmaxf(m1r, mx1);
        float mu0 = fmaxf(mn0, -1e30f), mu1 = fmaxf(mn1, -1e30f);
        float al0 = ex2(m0r - mu0), al1 = ex2(m1r - mu1);
        m0r = mn0; m1r = mn1;

        float rs0 = 0.f, rs1 = 0.f;
#pragma unroll
        for (int nt = 0; nt < 4; ++nt) {
            float p00 = ex2(s[nt][0] - mu0), p01 = ex2(s[nt][1] - mu0);
            float p10 = ex2(s[nt][2] - mu1), p11 = ex2(s[nt][3] - mu1);
            rs0 += p00 + p01; rs1 += p10 + p11;
            Ps[warp][g][nt * 8 + t4 * 2]         = __uint_as_float(f2tf(p00));
            Ps[warp][g][nt * 8 + t4 * 2 + 1]     = __uint_as_float(f2tf(p01));
            Ps[warp][g + 8][nt * 8 + t4 * 2]     = __uint_as_float(f2tf(p10));
            Ps[warp][g + 8][nt * 8 + t4 * 2 + 1] = __uint_as_float(f2tf(p11));
        }
        rs0 += __shfl_xor_sync(0xffffffffu, rs0, 1);
        rs0 += __shfl_xor_sync(0xffffffffu, rs0, 2);
        rs1 += __shfl_xor_sync(0xffffffffu, rs1, 1);
        rs1 += __shfl_xor_sync(0xffffffffu, rs1, 2);
        l0 = l0 * al0 + rs0;
        l1 = l1 * al1 + rs1;

#pragma unroll
        for (int nt = 0; nt < 16; ++nt) {
            acc[nt][0] *= al0; acc[nt][1] *= al0;
            acc[nt][2] *= al1; acc[nt][3] *= al1;
        }
        __syncwarp();

        // O += P . V
#pragma unroll
        for (int ks = 0; ks < 4; ++ks) {
            uint32_t a[4];
            a[0] = __float_as_uint(Ps[warp][g][ks * 8 + t4]);
            a[1] = __float_as_uint(Ps[warp][g + 8][ks * 8 + t4]);
            a[2] = __float_as_uint(Ps[warp][g][ks * 8 + t4 + 4]);
            a[3] = __float_as_uint(Ps[warp][g + 8][ks * 8 + t4 + 4]);
#pragma unroll
            for (int nt = 0; nt < 16; ++nt) {
                int vn = nt * 8 + g;
                int vk = ks * 8 + t4;
                uint32_t b0 = __float_as_uint(Vs[vk][vn]);
                uint32_t b1 = __float_as_uint(Vs[vk + 4][vn]);
                mma_tf32(acc[nt], a, b0, b1);
            }
        }
        __syncthreads();
    }

    if (nc == 1) {
        // single chunk: write final normalized output
        const float inv0 = 1.0f / l0, inv1 = 1.0f / l1;
#pragma unroll
        for (int nt = 0; nt < 16; ++nt) {
            int r = row_base + g;
            int c = nt * 8 + t4 * 2;
            out[(size_t)r * DH + c]           = acc[nt][0] * inv0;
            out[(size_t)r * DH + c + 1]       = acc[nt][1] * inv0;
            out[(size_t)(r + 8) * DH + c]     = acc[nt][2] * inv1;
            out[(size_t)(r + 8) * DH + c + 1] = acc[nt][3] * inv1;
        }
    } else {
        // write unnormalized partials + stats
        const int pslot = qt * MAXC + ch;
        float* Op = g_Opart + (size_t)pslot * 64 * DH;
        const int lr0 = warp * 16 + g, lr1 = lr0 + 8;
#pragma unroll
        for (int nt = 0; nt < 16; ++nt) {
            int c = nt * 8 + t4 * 2;
            Op[(size_t)lr0 * DH + c]     = acc[nt][0];
            Op[(size_t)lr0 * DH + c + 1] = acc[nt][1];
            Op[(size_t)lr1 * DH + c]     = acc[nt][2];
            Op[(size_t)lr1 * DH + c + 1] = acc[nt][3];
        }
        if (t4 == 0) {
            g_mpart[pslot * 64 + lr0] = m0r;
            g_lpart[pslot * 64 + lr0] = l0;
            g_mpart[pslot * 64 + lr1] = m1r;
            g_lpart[pslot * 64 + lr1] = l1;
        }
    }
}

// ---------------------------------------------------------------------------
// Combine partials for rows 512..4095 (q-tiles with >= 2 chunks).
// grid = 3584 blocks of 128 threads; one block per row, one thread per col.
// ---------------------------------------------------------------------------
__global__ __launch_bounds__(128)
void combine_kernel(float* __restrict__ out) {
    const int row = 512 + blockIdx.x;
    const int qt  = row >> 6;
    const int nc  = (qt >> 3) + 1;
    const int lr  = row & 63;
    const int col = threadIdx.x;

    float M = -1e30f;
    for (int c = 0; c < nc; ++c)
        M = fmaxf(M, g_mpart[(qt * MAXC + c) * 64 + lr]);

    float l = 0.f, o = 0.f;
    for (int c = 0; c < nc; ++c) {
        int pslot = qt * MAXC + c;
        float a = ex2(g_mpart[pslot * 64 + lr] - M);
        l += a * g_lpart[pslot * 64 + lr];
        o += a * g_Opart[((size_t)pslot * 64 + lr) * DH + col];
    }
    out[(size_t)row * DH + col] = o / l;
}

// ---------------------------------------------------------------------------

extern "C" void kernel_launch(void* const* d_in, const int* in_sizes, int n_in,
                              void* d_out, int out_size) {
    (void)in_sizes; (void)n_in; (void)out_size;
    const float* xq = (const float*)d_in[0];
    const float* xk = (const float*)d_in[1];
    const float* xv = (const float*)d_in[2];
    const float* wq = (const float*)d_in[3];
    const float* bq = (const float*)d_in[4];
    const float* wk = (const float*)d_in[5];
    const float* bk = (const float*)d_in[6];
    const float* wv = (const float*)d_in[7];
    const float* bv = (const float*)d_in[8];
    float* out = (float*)d_out;

    proj_kernel<<<dim3(SEQ / 64, 3), 256>>>(xq, xk, xv, wq, bq, wk, bk, wv, bv);
    attn_kernel<<<dim3(SEQ / BM, MAXC), 128>>>(out);
    combine_kernel<<<SEQ - 512, 128>>>(out);
}